// round 15
// baseline (speedup 1.0000x reference)
#include <cuda_runtime.h>
#include <math.h>

typedef unsigned long long u64;

#define NTOK 8192
#define HDIM 2048
#define NEXP 32
#define RDIM 16
#define ADIM 32
#define CAP  1024
#define KC   64

// ---------------- static device scratch ------------------------------------
__device__ float d_aw[NEXP];
__device__ int   d_cnt[NEXP];
__device__ int   d_items[NEXP * CAP];           // token*2 + slot
__device__ float d_coef[NTOK * 2];
__device__ float d_Ut[NEXP * RDIM * HDIM];      // 4MB, r-major U
__device__ float d_A[NEXP * CAP * RDIM];        // 2MB, coef-folded hU
__device__ float d_p1[NTOK * HDIM];             // 64MB slot-1 partials

// ---------------- packed f32x2 + cp.async helpers ---------------------------
__device__ __forceinline__ void fma2(u64 &d, u64 a, u64 b) {
    asm("fma.rn.f32x2 %0, %1, %2, %0;" : "+l"(d) : "l"(a), "l"(b));
}
__device__ __forceinline__ u64 dup2(float a) {
    u64 r; asm("mov.b64 %0, {%1, %1};" : "=l"(r) : "f"(a)); return r;
}
__device__ __forceinline__ float lo32(u64 v) { return __uint_as_float((unsigned)v); }
__device__ __forceinline__ float hi32(u64 v) { return __uint_as_float((unsigned)(v >> 32)); }

__device__ __forceinline__ void cpa16(void* dst, const void* src) {
    unsigned d = (unsigned)__cvta_generic_to_shared(dst);
    asm volatile("cp.async.cg.shared.global [%0], [%1], 16;" :: "r"(d), "l"(src));
}
#define CP_COMMIT()  asm volatile("cp.async.commit_group;")
#define CP_WAIT0()   asm volatile("cp.async.wait_group 0;")
#define CP_WAIT1()   asm volatile("cp.async.wait_group 1;")

// ============ kernel 1: prep (Ut transpose, aw, counter reset) =============
__global__ __launch_bounds__(256) void prep_kernel(
    const float* __restrict__ U, const float* __restrict__ attr,
    const float* __restrict__ Wa)
{
    __shared__ float ts[RDIM][129];
    int t  = threadIdx.x;
    int s  = blockIdx.x >> 4;
    int k0 = (blockIdx.x & 15) * 128;

    const float* src = U + ((size_t)s * HDIM + k0) * RDIM;
    #pragma unroll
    for (int i = 0; i < 8; i++) {
        int e = t + 256 * i;            // e = kl*16 + r
        ts[e & 15][e >> 4] = src[e];
    }
    __syncthreads();
    #pragma unroll
    for (int i = 0; i < 8; i++) {
        int o = t + 256 * i;            // o = r*128 + kl
        int r = o >> 7, kl = o & 127;
        d_Ut[((size_t)s * RDIM + r) * HDIM + k0 + kl] = ts[r][kl];
    }

    if (blockIdx.x == 0 && t < NEXP) {
        d_cnt[t] = 0;
        float acc = 0.f;
        #pragma unroll
        for (int dd = 0; dd < ADIM; dd++) acc += attr[t * ADIM + dd] * Wa[dd];
        d_aw[t] = 1.f / (1.f + expf(-acc));
    }
}

// ============ kernel 2: router (16 tokens per CTA, 512 CTAs) ===============
__global__ __launch_bounds__(256) void router_kernel(
    const float* __restrict__ h, const float* __restrict__ Wr)
{
    __shared__ float Hs[2][16][KC + 4];     // 272B rows: odd 16B units
    __shared__ float Ws[2][32][KC + 4];
    __shared__ float scS[16][NEXP + 1];

    int t  = threadIdx.x;
    int tb = blockIdx.x * 16;
    int s  = t & 31;          // lane -> expert
    int tg = t >> 5;          // warp -> 2-token group

    u64 acc0 = 0ull, acc1 = 0ull;

    #define R_STAGE(b, kc) {                                                  \
        int k0_ = (kc) * KC;                                                  \
        {   int row = t >> 4, q = t & 15;                                     \
            cpa16(&Hs[b][row][q * 4],                                         \
                  &h[(size_t)(tb + row) * HDIM + k0_ + q * 4]); }             \
        _Pragma("unroll")                                                     \
        for (int j = 0; j < 2; j++) {                                         \
            int idx = t + 256 * j;                                            \
            int row = idx >> 4, q = idx & 15;                                 \
            cpa16(&Ws[b][row][q * 4],                                         \
                  &Wr[(size_t)row * HDIM + k0_ + q * 4]);                     \
        }                                                                     \
        CP_COMMIT(); }

    R_STAGE(0, 0);
    int buf = 0;
    for (int kc = 0; kc < HDIM / KC; kc++) {
        if (kc + 1 < HDIM / KC) { R_STAGE(buf ^ 1, kc + 1); CP_WAIT1(); }
        else                    { CP_WAIT0(); }
        __syncthreads();
        const float* Wp = &Ws[buf][s][0];
        const float* Hp0 = &Hs[buf][tg * 2][0];
        const float* Hp1 = Hp0 + (KC + 4);
        #pragma unroll 4
        for (int kk = 0; kk < KC; kk += 4) {
            ulonglong2 w  = *(const ulonglong2*)(Wp + kk);
            ulonglong2 h0 = *(const ulonglong2*)(Hp0 + kk);
            ulonglong2 h1 = *(const ulonglong2*)(Hp1 + kk);
            fma2(acc0, h0.x, w.x); fma2(acc0, h0.y, w.y);
            fma2(acc1, h1.x, w.x); fma2(acc1, h1.y, w.y);
        }
        __syncthreads();
        buf ^= 1;
    }
    scS[tg * 2][s]     = lo32(acc0) + hi32(acc0);
    scS[tg * 2 + 1][s] = lo32(acc1) + hi32(acc1);
    __syncthreads();

    if (t < 16) {
        int token = tb + t;
        float v1 = -1e30f, v2 = -1e30f; int i1 = 0, i2 = 0;
        #pragma unroll
        for (int ss = 0; ss < NEXP; ss++) {
            float v = scS[t][ss];
            if (v > v1)      { v2 = v1; i2 = i1; v1 = v; i1 = ss; }
            else if (v > v2) { v2 = v;  i2 = ss; }
        }
        float Z = 0.f;
        #pragma unroll
        for (int ss = 0; ss < NEXP; ss++) Z += expf(scS[t][ss] - v1);
        float g1 = 1.f / Z;
        float g2 = expf(v2 - v1) / Z;
        float inv = 1.f / (g1 + g2 + 1e-8f);
        g1 *= inv; g2 *= inv;
        float scale = 0.9f + 0.2f * (g1 * d_aw[i1] + g2 * d_aw[i2]);
        d_coef[token * 2]     = scale * g1;
        d_coef[token * 2 + 1] = scale * g2;
        int p1 = atomicAdd(&d_cnt[i1], 1);
        if (p1 < CAP) d_items[i1 * CAP + p1] = token * 2;
        int p2 = atomicAdd(&d_cnt[i2], 1);
        if (p2 < CAP) d_items[i2 * CAP + p2] = token * 2 + 1;
    }
}

// ============ kernel 3a: moe1 — A[assign][16] = gathered H @ Ut[s]^T =======
// 64-row tiles, grid = 32*16 = 512. Static smem ~44KB.
__global__ __launch_bounds__(256, 2) void moe1_kernel(const float* __restrict__ h)
{
    __shared__ int   itemS[64];
    __shared__ float coefS[64];
    __shared__ float Hs[2][64][KC + 4];
    __shared__ float Us[2][16][KC + 4];

    int t    = threadIdx.x;
    int s    = blockIdx.x >> 4;
    int tile = blockIdx.x & 15;
    int n    = min(d_cnt[s], CAP);
    int base = tile * 64;
    if (base >= n) return;
    int cnt = min(64, n - base);

    if (t < 64) {
        if (t < cnt) {
            int item = d_items[s * CAP + base + t];
            itemS[t] = item;
            coefS[t] = d_coef[item];
        } else { itemS[t] = 0; coefS[t] = 0.f; }
    }
    __syncthreads();

    #define M1_STAGE(b, kc) {                                                 \
        int k0_ = (kc) * KC;                                                  \
        int row0 = t >> 4, q_ = t & 15;                                       \
        _Pragma("unroll")                                                     \
        for (int p = 0; p < 4; p++) {                                         \
            int row = row0 + 16 * p;                                          \
            int tok = itemS[row] >> 1;                                        \
            cpa16(&Hs[b][row][q_ * 4],                                        \
                  &h[(size_t)tok * HDIM + k0_ + q_ * 4]);                     \
        }                                                                     \
        cpa16(&Us[b][row0][q_ * 4],                                           \
              &d_Ut[((size_t)s * RDIM + row0) * HDIM + k0_ + q_ * 4]);        \
        CP_COMMIT(); }

    int mg = t >> 3;          // rows mg*2, mg*2+1
    int rq = t & 7;           // r = rq and rq+8 (17x16B row step: odd)
    u64 a00 = 0, a01 = 0, a10 = 0, a11 = 0;   // [row][r]

    M1_STAGE(0, 0);
    int buf = 0;
    for (int kc = 0; kc < HDIM / KC; kc++) {
        if (kc + 1 < HDIM / KC) { M1_STAGE(buf ^ 1, kc + 1); CP_WAIT1(); }
        else                    { CP_WAIT0(); }
        __syncthreads();
        const float* Hp0 = &Hs[buf][mg * 2][0];
        const float* Hp1 = Hp0 + (KC + 4);
        const float* Up0 = &Us[buf][rq][0];
        const float* Up1 = &Us[buf][rq + 8][0];
        #pragma unroll 4
        for (int kk = 0; kk < KC; kk += 4) {
            ulonglong2 u0 = *(const ulonglong2*)(Up0 + kk);
            ulonglong2 u1 = *(const ulonglong2*)(Up1 + kk);
            ulonglong2 h0 = *(const ulonglong2*)(Hp0 + kk);
            ulonglong2 h1 = *(const ulonglong2*)(Hp1 + kk);
            fma2(a00, h0.x, u0.x); fma2(a00, h0.y, u0.y);
            fma2(a01, h0.x, u1.x); fma2(a01, h0.y, u1.y);
            fma2(a10, h1.x, u0.x); fma2(a10, h1.y, u0.y);
            fma2(a11, h1.x, u1.x); fma2(a11, h1.y, u1.y);
        }
        __syncthreads();
        buf ^= 1;
    }
    {
        float cf0 = coefS[mg * 2], cf1 = coefS[mg * 2 + 1];
        float* A0 = &d_A[((size_t)(s * CAP + base + mg * 2)) * RDIM];
        float* A1 = A0 + RDIM;
        A0[rq]     = cf0 * (lo32(a00) + hi32(a00));
        A0[rq + 8] = cf0 * (lo32(a01) + hi32(a01));
        A1[rq]     = cf1 * (lo32(a10) + hi32(a10));
        A1[rq + 8] = cf1 * (lo32(a11) + hi32(a11));
    }
}

// ============ kernel 3b: moe2 — Out[64][128] = A-tile @ V-chunk ============
// grid = 32 experts x 16 row-tiles x 16 col-chunks = 8192 CTAs.
// Per thread: 2 rows x 16 cols; Vs LDS shared across rows; As via float4/4r.
__global__ __launch_bounds__(256) void moe2_kernel(
    const float* __restrict__ V, float* __restrict__ out)
{
    __shared__ int   itemS[64];
    __shared__ float As[64][16];       // 64B rows: cp.async-aligned; reads broadcast
    __shared__ float Vs[16][132];      // 528B rows = 33x16B (odd) -> conflict-free

    int t  = threadIdx.x;
    int s  = blockIdx.x >> 8;
    int rt = (blockIdx.x >> 4) & 15;
    int cc = blockIdx.x & 15;
    int n    = min(d_cnt[s], CAP);
    int base = rt * 64;
    if (base >= n) return;
    int cnt = min(64, n - base);

    if (t < 64) itemS[t] = (t < cnt) ? d_items[s * CAP + base + t] : -1;
    {   // stage A: 64 rows x 4 quads
        int m = t >> 2, q = t & 3;
        cpa16(&As[m][q * 4], &d_A[((size_t)(s * CAP + base + m)) * RDIM + q * 4]);
    }
    {   // stage V chunk: 16 r x 32 quads
        #pragma unroll
        for (int j = 0; j < 2; j++) {
            int idx = t + 256 * j;
            int rr = idx >> 5, q = idx & 31;
            cpa16(&Vs[rr][q * 4],
                  &V[((size_t)s * RDIM + rr) * HDIM + cc * 128 + q * 4]);
        }
    }
    CP_COMMIT(); CP_WAIT0();
    __syncthreads();

    int rg = t >> 3;            // 0..31 -> rows rg*2, rg*2+1
    int cg = t & 7;             // quads at cg*4 + j*32 (lanes 0-7 contiguous)
    u64 oa[2][8];
    #pragma unroll
    for (int i = 0; i < 2; i++)
        #pragma unroll
        for (int j = 0; j < 8; j++) oa[i][j] = 0ull;

    #pragma unroll
    for (int rb = 0; rb < 4; rb++) {
        float4 a0 = *(const float4*)&As[rg * 2][rb * 4];
        float4 a1 = *(const float4*)&As[rg * 2 + 1][rb * 4];
        const float* af0 = (const float*)&a0;
        const float* af1 = (const float*)&a1;
        #pragma unroll
        for (int rr = 0; rr < 4; rr++) {
            int r = rb * 4 + rr;
            u64 b0 = dup2(af0[rr]);
            u64 b1 = dup2(af1[rr]);
            #pragma unroll
            for (int j = 0; j < 4; j++) {
                ulonglong2 v = *(const ulonglong2*)&Vs[r][cg * 4 + j * 32];
                fma2(oa[0][j * 2],     b0, v.x);
                fma2(oa[0][j * 2 + 1], b0, v.y);
                fma2(oa[1][j * 2],     b1, v.x);
                fma2(oa[1][j * 2 + 1], b1, v.y);
            }
        }
    }
    #pragma unroll
    for (int i = 0; i < 2; i++) {
        int row = rg * 2 + i;
        if (row < cnt) {
            int item  = itemS[row];
            int token = item >> 1;
            float* dst = ((item & 1) ? d_p1 : out)
                         + (size_t)token * HDIM + cc * 128;
            #pragma unroll
            for (int j = 0; j < 4; j++)
                *(float4*)(dst + cg * 4 + j * 32) =
                    make_float4(lo32(oa[i][j * 2]),     hi32(oa[i][j * 2]),
                                lo32(oa[i][j * 2 + 1]), hi32(oa[i][j * 2 + 1]));
        }
    }
}

// ============ kernel 4: combine slot-0 (out) + slot-1 (d_p1) ===============
__global__ __launch_bounds__(256) void combine_kernel(float* __restrict__ out)
{
    int i = blockIdx.x * 256 + threadIdx.x;
    float4 a = ((const float4*)out)[i];
    float4 b = ((const float4*)d_p1)[i];
    a.x += b.x; a.y += b.y; a.z += b.z; a.w += b.w;
    ((float4*)out)[i] = a;
}

// ===========================================================================
extern "C" void kernel_launch(void* const* d_in, const int* in_sizes, int n_in,
                              void* d_out, int out_size)
{
    const float* h    = (const float*)d_in[0];
    const float* Wr   = (const float*)d_in[1];
    const float* U    = (const float*)d_in[2];
    const float* V    = (const float*)d_in[3];
    const float* attr = (const float*)d_in[4];
    const float* Wa   = (const float*)d_in[5];
    float* out = (float*)d_out;

    prep_kernel<<<512, 256>>>(U, attr, Wa);
    router_kernel<<<NTOK / 16, 256>>>(h, Wr);
    moe1_kernel<<<NEXP * 16, 256>>>(h);
    moe2_kernel<<<NEXP * 16 * 16, 256>>>(V, out);
    combine_kernel<<<NTOK * HDIM / 4 / 256, 256>>>(out);
}

// round 16
// speedup vs baseline: 1.1203x; 1.1203x over previous
#include <cuda_runtime.h>
#include <math.h>

typedef unsigned long long u64;

#define NTOK 8192
#define HDIM 2048
#define NEXP 32
#define RDIM 16
#define ADIM 32
#define CAP  1024
#define KC   64

// ---------------- static device scratch ------------------------------------
__device__ float  d_aw[NEXP];
__device__ int    d_cnt[NEXP];
__device__ int    d_items[NEXP * CAP];          // token*2 + slot
__device__ float  d_coef[NTOK * 2];
__device__ float  d_Ut[NEXP * RDIM * HDIM];     // 4MB, r-major U
__device__ float  d_A[NEXP * CAP * RDIM];       // 2MB, coef-folded hU
__device__ float2 d_Vp[NEXP * 8 * HDIM];        // 4MB, r-paired V

// ---------------- packed f32x2 + cp.async + red helpers ---------------------
__device__ __forceinline__ void fma2(u64 &d, u64 a, u64 b) {
    asm("fma.rn.f32x2 %0, %1, %2, %0;" : "+l"(d) : "l"(a), "l"(b));
}
__device__ __forceinline__ float lo32(u64 v) { return __uint_as_float((unsigned)v); }
__device__ __forceinline__ float hi32(u64 v) { return __uint_as_float((unsigned)(v >> 32)); }
__device__ __forceinline__ float hsum(u64 v) { return lo32(v) + hi32(v); }

__device__ __forceinline__ void cpa16(void* dst, const void* src) {
    unsigned d = (unsigned)__cvta_generic_to_shared(dst);
    asm volatile("cp.async.cg.shared.global [%0], [%1], 16;" :: "r"(d), "l"(src));
}
#define CP_COMMIT()  asm volatile("cp.async.commit_group;")
#define CP_WAIT0()   asm volatile("cp.async.wait_group 0;")
#define CP_WAIT1()   asm volatile("cp.async.wait_group 1;")

__device__ __forceinline__ void red4(float* addr, float x, float y, float z, float w) {
    asm volatile("red.global.add.v4.f32 [%0], {%1, %2, %3, %4};"
                 :: "l"(addr), "f"(x), "f"(y), "f"(z), "f"(w) : "memory");
}

// ============ kernel 0: zero the output ====================================
__global__ __launch_bounds__(256) void zero_kernel(float* __restrict__ out)
{
    int i = blockIdx.x * 256 + threadIdx.x;
    ((float4*)out)[i] = make_float4(0.f, 0.f, 0.f, 0.f);
}

// ============ kernel 1: prep (Ut transpose, Vp pack, aw, counters) =========
__global__ __launch_bounds__(256) void prep_kernel(
    const float* __restrict__ U, const float* __restrict__ V,
    const float* __restrict__ attr, const float* __restrict__ Wa)
{
    __shared__ float ts[RDIM][129];
    int t  = threadIdx.x;
    int s  = blockIdx.x >> 4;
    int k0 = (blockIdx.x & 15) * 128;

    // --- Ut transpose ---
    const float* src = U + ((size_t)s * HDIM + k0) * RDIM;
    #pragma unroll
    for (int i = 0; i < 8; i++) {
        int e = t + 256 * i;            // e = kl*16 + r
        ts[e & 15][e >> 4] = src[e];
    }
    __syncthreads();
    #pragma unroll
    for (int i = 0; i < 8; i++) {
        int o = t + 256 * i;            // o = r*128 + kl
        int r = o >> 7, kl = o & 127;
        d_Ut[((size_t)s * RDIM + r) * HDIM + k0 + kl] = ts[r][kl];
    }

    // --- Vp pack: Vp[s][rp][c] = {V[s][2rp][c], V[s][2rp+1][c]} ------------
    #pragma unroll
    for (int j = 0; j < 4; j++) {
        int idx = blockIdx.x * 1024 + t + 256 * j;   // 512*1024 = 524288 total
        int ss  = idx >> 14;
        int rem = idx & 16383;
        int rp  = rem >> 11;
        int c   = rem & 2047;
        const float* vb = V + ((size_t)ss * RDIM + 2 * rp) * HDIM + c;
        d_Vp[idx] = make_float2(vb[0], vb[HDIM]);
    }

    if (blockIdx.x == 0 && t < NEXP) {
        d_cnt[t] = 0;
        float acc = 0.f;
        #pragma unroll
        for (int dd = 0; dd < ADIM; dd++) acc += attr[t * ADIM + dd] * Wa[dd];
        d_aw[t] = 1.f / (1.f + expf(-acc));
    }
}

// ============ kernel 2: router (32 tokens per CTA, 256 CTAs) ===============
__global__ __launch_bounds__(256) void router_kernel(
    const float* __restrict__ h, const float* __restrict__ Wr)
{
    __shared__ float Hs[2][32][KC + 4];     // 272B rows: odd 16B units
    __shared__ float Ws[2][32][KC + 4];
    __shared__ float scS[32][NEXP + 1];

    int t  = threadIdx.x;
    int tb = blockIdx.x * 32;
    int s  = t & 31;          // lane -> expert
    int tg = t >> 5;          // warp -> 4-token group

    u64 acc[4];
    #pragma unroll
    for (int i = 0; i < 4; i++) acc[i] = 0ull;

    #define R_STAGE(b, kc) {                                                  \
        int k0_ = (kc) * KC;                                                  \
        _Pragma("unroll")                                                     \
        for (int j = 0; j < 2; j++) {                                         \
            int idx = t + 256 * j;                                            \
            int row = idx >> 4, q = idx & 15;                                 \
            cpa16(&Hs[b][row][q * 4],                                         \
                  &h[(size_t)(tb + row) * HDIM + k0_ + q * 4]);               \
            cpa16(&Ws[b][row][q * 4],                                         \
                  &Wr[(size_t)row * HDIM + k0_ + q * 4]);                     \
        }                                                                     \
        CP_COMMIT(); }

    R_STAGE(0, 0);
    int buf = 0;
    for (int kc = 0; kc < HDIM / KC; kc++) {
        if (kc + 1 < HDIM / KC) { R_STAGE(buf ^ 1, kc + 1); CP_WAIT1(); }
        else                    { CP_WAIT0(); }
        __syncthreads();
        const float* Wp = &Ws[buf][s][0];
        const float* Hp = &Hs[buf][tg * 4][0];
        #pragma unroll 4
        for (int kk = 0; kk < KC; kk += 4) {
            ulonglong2 w = *(const ulonglong2*)(Wp + kk);
            #pragma unroll
            for (int i = 0; i < 4; i++) {
                ulonglong2 hh = *(const ulonglong2*)(Hp + i * (KC + 4) + kk);
                fma2(acc[i], hh.x, w.x);
                fma2(acc[i], hh.y, w.y);
            }
        }
        __syncthreads();
        buf ^= 1;
    }
    #pragma unroll
    for (int i = 0; i < 4; i++) scS[tg * 4 + i][s] = hsum(acc[i]);
    __syncthreads();

    if (t < 32) {
        int token = tb + t;
        float v1 = -1e30f, v2 = -1e30f; int i1 = 0, i2 = 0;
        #pragma unroll
        for (int ss = 0; ss < NEXP; ss++) {
            float v = scS[t][ss];
            if (v > v1)      { v2 = v1; i2 = i1; v1 = v; i1 = ss; }
            else if (v > v2) { v2 = v;  i2 = ss; }
        }
        float Z = 0.f;
        #pragma unroll
        for (int ss = 0; ss < NEXP; ss++) Z += expf(scS[t][ss] - v1);
        float g1 = 1.f / Z;
        float g2 = expf(v2 - v1) / Z;
        float inv = 1.f / (g1 + g2 + 1e-8f);
        g1 *= inv; g2 *= inv;
        float scale = 0.9f + 0.2f * (g1 * d_aw[i1] + g2 * d_aw[i2]);
        d_coef[token * 2]     = scale * g1;
        d_coef[token * 2 + 1] = scale * g2;
        int p1 = atomicAdd(&d_cnt[i1], 1);
        if (p1 < CAP) d_items[i1 * CAP + p1] = token * 2;
        int p2 = atomicAdd(&d_cnt[i2], 1);
        if (p2 < CAP) d_items[i2 * CAP + p2] = token * 2 + 1;
    }
}

// ============ kernel 3a: moe1 — A[assign][16] = gathered H @ Ut[s]^T =======
// 64-row tiles, grid = 32*16 = 512. Static smem ~44KB.
__global__ __launch_bounds__(256, 2) void moe1_kernel(const float* __restrict__ h)
{
    __shared__ int   itemS[64];
    __shared__ float coefS[64];
    __shared__ float Hs[2][64][KC + 4];
    __shared__ float Us[2][16][KC + 4];

    int t    = threadIdx.x;
    int s    = blockIdx.x >> 4;
    int tile = blockIdx.x & 15;
    int n    = min(d_cnt[s], CAP);
    int base = tile * 64;
    if (base >= n) return;
    int cnt = min(64, n - base);

    if (t < 64) {
        if (t < cnt) {
            int item = d_items[s * CAP + base + t];
            itemS[t] = item;
            coefS[t] = d_coef[item];
        } else { itemS[t] = 0; coefS[t] = 0.f; }
    }
    __syncthreads();

    #define M1_STAGE(b, kc) {                                                 \
        int k0_ = (kc) * KC;                                                  \
        int row0 = t >> 4, q_ = t & 15;                                       \
        _Pragma("unroll")                                                     \
        for (int p = 0; p < 4; p++) {                                         \
            int row = row0 + 16 * p;                                          \
            int tok = itemS[row] >> 1;                                        \
            cpa16(&Hs[b][row][q_ * 4],                                        \
                  &h[(size_t)tok * HDIM + k0_ + q_ * 4]);                     \
        }                                                                     \
        cpa16(&Us[b][row0][q_ * 4],                                           \
              &d_Ut[((size_t)s * RDIM + row0) * HDIM + k0_ + q_ * 4]);        \
        CP_COMMIT(); }

    int mg = t >> 3;          // rows mg*2, mg*2+1
    int rq = t & 7;           // r = rq and rq+8 (17x16B row step: odd)
    u64 a00 = 0, a01 = 0, a10 = 0, a11 = 0;   // [row][r]

    M1_STAGE(0, 0);
    int buf = 0;
    for (int kc = 0; kc < HDIM / KC; kc++) {
        if (kc + 1 < HDIM / KC) { M1_STAGE(buf ^ 1, kc + 1); CP_WAIT1(); }
        else                    { CP_WAIT0(); }
        __syncthreads();
        const float* Hp0 = &Hs[buf][mg * 2][0];
        const float* Hp1 = Hp0 + (KC + 4);
        const float* Up0 = &Us[buf][rq][0];
        const float* Up1 = &Us[buf][rq + 8][0];
        #pragma unroll 4
        for (int kk = 0; kk < KC; kk += 4) {
            ulonglong2 u0 = *(const ulonglong2*)(Up0 + kk);
            ulonglong2 u1 = *(const ulonglong2*)(Up1 + kk);
            ulonglong2 h0 = *(const ulonglong2*)(Hp0 + kk);
            ulonglong2 h1 = *(const ulonglong2*)(Hp1 + kk);
            fma2(a00, h0.x, u0.x); fma2(a00, h0.y, u0.y);
            fma2(a01, h0.x, u1.x); fma2(a01, h0.y, u1.y);
            fma2(a10, h1.x, u0.x); fma2(a10, h1.y, u0.y);
            fma2(a11, h1.x, u1.x); fma2(a11, h1.y, u1.y);
        }
        __syncthreads();
        buf ^= 1;
    }
    {
        float cf0 = coefS[mg * 2], cf1 = coefS[mg * 2 + 1];
        float* A0 = &d_A[((size_t)(s * CAP + base + mg * 2)) * RDIM];
        float* A1 = A0 + RDIM;
        A0[rq]     = cf0 * hsum(a00);
        A0[rq + 8] = cf0 * hsum(a01);
        A1[rq]     = cf1 * hsum(a10);
        A1[rq + 8] = cf1 * hsum(a11);
    }
}

// ============ kernel 3b: moe2 — out[64][128] += A-tile @ Vp-chunk ==========
// grid = 32 experts x 16 row-tiles x 16 col-chunks = 8192 CTAs.
// r-paired: fma2 packs (2rp, 2rp+1); A pairs are native u64; no dup MOVs.
// Both slots red.global straight into out (zeroed beforehand).
__global__ __launch_bounds__(256) void moe2_kernel(
    float* __restrict__ out)
{
    __shared__ int    itemS[64];
    __shared__ float  As[64][16];      // 64B rows: cp.async-aligned; u64 reads broadcast
    __shared__ float2 Vs[8][130];      // 1040B rows = 65x16B (odd) -> conflict-free

    int t  = threadIdx.x;
    int s  = blockIdx.x >> 8;
    int rt = (blockIdx.x >> 4) & 15;
    int cc = blockIdx.x & 15;
    int n    = min(d_cnt[s], CAP);
    int base = rt * 64;
    if (base >= n) return;
    int cnt = min(64, n - base);

    if (t < 64) itemS[t] = (t < cnt) ? d_items[s * CAP + base + t] : -1;
    {   // stage A: 64 rows x 4 quads
        int m = t >> 2, q = t & 3;
        cpa16(&As[m][q * 4], &d_A[((size_t)(s * CAP + base + m)) * RDIM + q * 4]);
    }
    {   // stage Vp chunk: 8 rp x 128 cols (float2) = 512 x 16B
        #pragma unroll
        for (int j = 0; j < 2; j++) {
            int idx = t + 256 * j;
            int rp = idx >> 6, q = idx & 63;
            cpa16(&Vs[rp][q * 2],
                  &d_Vp[((size_t)(s * 8 + rp)) * HDIM + cc * 128 + q * 2]);
        }
    }
    CP_COMMIT(); CP_WAIT0();
    __syncthreads();

    int rg = t >> 5;            // warp -> 4-row group (per phase)
    int c0 = (t & 31) * 4;      // 4 cols per lane (contiguous per warp)

    #pragma unroll
    for (int ph = 0; ph < 2; ph++) {
        int rbase = ph * 32 + rg * 4;
        u64 oa[4][4];
        #pragma unroll
        for (int i = 0; i < 4; i++)
            #pragma unroll
            for (int j = 0; j < 4; j++) oa[i][j] = 0ull;

        #pragma unroll
        for (int rp = 0; rp < 8; rp++) {
            ulonglong2 v01 = *(const ulonglong2*)&Vs[rp][c0];       // cols c0, c0+1
            ulonglong2 v23 = *(const ulonglong2*)&Vs[rp][c0 + 2];   // cols c0+2, c0+3
            #pragma unroll
            for (int i = 0; i < 4; i++) {
                u64 ap = *(const u64*)&As[rbase + i][rp * 2];       // {A[2rp],A[2rp+1]}
                fma2(oa[i][0], ap, v01.x);
                fma2(oa[i][1], ap, v01.y);
                fma2(oa[i][2], ap, v23.x);
                fma2(oa[i][3], ap, v23.y);
            }
        }
        #pragma unroll
        for (int i = 0; i < 4; i++) {
            int row = rbase + i;
            if (row < cnt) {
                int token = itemS[row] >> 1;
                float* dst = out + (size_t)token * HDIM + cc * 128 + c0;
                red4(dst, hsum(oa[i][0]), hsum(oa[i][1]),
                          hsum(oa[i][2]), hsum(oa[i][3]));
            }
        }
    }
}

// ===========================================================================
extern "C" void kernel_launch(void* const* d_in, const int* in_sizes, int n_in,
                              void* d_out, int out_size)
{
    const float* h    = (const float*)d_in[0];
    const float* Wr   = (const float*)d_in[1];
    const float* U    = (const float*)d_in[2];
    const float* V    = (const float*)d_in[3];
    const float* attr = (const float*)d_in[4];
    const float* Wa   = (const float*)d_in[5];
    float* out = (float*)d_out;

    zero_kernel<<<NTOK * HDIM / 4 / 256, 256>>>(out);
    prep_kernel<<<512, 256>>>(U, V, attr, Wa);
    router_kernel<<<NTOK / 32, 256>>>(h, Wr);
    moe1_kernel<<<NEXP * 16, 256>>>(h);
    moe2_kernel<<<NEXP * 16 * 16, 256>>>(out);
}

// round 17
// speedup vs baseline: 1.2982x; 1.1587x over previous
#include <cuda_runtime.h>
#include <math.h>

typedef unsigned long long u64;

#define NTOK 8192
#define HDIM 2048
#define NEXP 32
#define RDIM 16
#define ADIM 32
#define CAP  1024
#define KC   64

// ---------------- static device scratch ------------------------------------
__device__ float  d_aw[NEXP];
__device__ int    d_cnt[NEXP];
__device__ int    d_items[NEXP * CAP];          // token*2 + slot
__device__ float  d_coef[NTOK * 2];
__device__ float  d_A[NEXP * CAP * RDIM];       // 2MB, coef-folded hU
__device__ float2 d_Vp[NEXP * 8 * HDIM];        // 4MB, r-paired V

// ---------------- packed f32x2 + cp.async + red helpers ---------------------
__device__ __forceinline__ void fma2(u64 &d, u64 a, u64 b) {
    asm("fma.rn.f32x2 %0, %1, %2, %0;" : "+l"(d) : "l"(a), "l"(b));
}
__device__ __forceinline__ u64 dup2(float a) {
    u64 r; asm("mov.b64 %0, {%1, %1};" : "=l"(r) : "f"(a)); return r;
}
__device__ __forceinline__ float lo32(u64 v) { return __uint_as_float((unsigned)v); }
__device__ __forceinline__ float hi32(u64 v) { return __uint_as_float((unsigned)(v >> 32)); }
__device__ __forceinline__ float hsum(u64 v) { return lo32(v) + hi32(v); }

__device__ __forceinline__ void cpa16(void* dst, const void* src) {
    unsigned d = (unsigned)__cvta_generic_to_shared(dst);
    asm volatile("cp.async.cg.shared.global [%0], [%1], 16;" :: "r"(d), "l"(src));
}
#define CP_COMMIT()  asm volatile("cp.async.commit_group;")
#define CP_WAIT0()   asm volatile("cp.async.wait_group 0;")
#define CP_WAIT1()   asm volatile("cp.async.wait_group 1;")

__device__ __forceinline__ void red4(float* addr, float x, float y, float z, float w) {
    asm volatile("red.global.add.v4.f32 [%0], {%1, %2, %3, %4};"
                 :: "l"(addr), "f"(x), "f"(y), "f"(z), "f"(w) : "memory");
}

// ============ kernel 0: zero the output ====================================
__global__ __launch_bounds__(256) void zero_kernel(float* __restrict__ out)
{
    int i = blockIdx.x * 256 + threadIdx.x;
    ((float4*)out)[i] = make_float4(0.f, 0.f, 0.f, 0.f);
}

// ============ kernel 1: prep (Vp pack, aw, counters) — no transpose needed =
__global__ __launch_bounds__(256) void prep_kernel(
    const float* __restrict__ V, const float* __restrict__ attr,
    const float* __restrict__ Wa)
{
    int t = threadIdx.x;

    // Vp pack: Vp[s][rp][c] = {V[s][2rp][c], V[s][2rp+1][c]}
    #pragma unroll
    for (int j = 0; j < 4; j++) {
        int idx = blockIdx.x * 1024 + t + 256 * j;   // 512*1024 = 524288 total
        int ss  = idx >> 14;
        int rem = idx & 16383;
        int rp  = rem >> 11;
        int c   = rem & 2047;
        const float* vb = V + ((size_t)ss * RDIM + 2 * rp) * HDIM + c;
        d_Vp[idx] = make_float2(vb[0], vb[HDIM]);
    }

    if (blockIdx.x == 0 && t < NEXP) {
        d_cnt[t] = 0;
        float acc = 0.f;
        #pragma unroll
        for (int dd = 0; dd < ADIM; dd++) acc += attr[t * ADIM + dd] * Wa[dd];
        d_aw[t] = 1.f / (1.f + expf(-acc));
    }
}

// ============ kernel 2: router (32 tokens per CTA, 256 CTAs) ===============
__global__ __launch_bounds__(256) void router_kernel(
    const float* __restrict__ h, const float* __restrict__ Wr)
{
    __shared__ float Hs[2][32][KC + 4];     // 272B rows: odd 16B units
    __shared__ float Ws[2][32][KC + 4];
    __shared__ float scS[32][NEXP + 1];

    int t  = threadIdx.x;
    int tb = blockIdx.x * 32;
    int s  = t & 31;          // lane -> expert
    int tg = t >> 5;          // warp -> 4-token group

    u64 acc[4];
    #pragma unroll
    for (int i = 0; i < 4; i++) acc[i] = 0ull;

    #define R_STAGE(b, kc) {                                                  \
        int k0_ = (kc) * KC;                                                  \
        _Pragma("unroll")                                                     \
        for (int j = 0; j < 2; j++) {                                         \
            int idx = t + 256 * j;                                            \
            int row = idx >> 4, q = idx & 15;                                 \
            cpa16(&Hs[b][row][q * 4],                                         \
                  &h[(size_t)(tb + row) * HDIM + k0_ + q * 4]);               \
            cpa16(&Ws[b][row][q * 4],                                         \
                  &Wr[(size_t)row * HDIM + k0_ + q * 4]);                     \
        }                                                                     \
        CP_COMMIT(); }

    R_STAGE(0, 0);
    int buf = 0;
    for (int kc = 0; kc < HDIM / KC; kc++) {
        if (kc + 1 < HDIM / KC) { R_STAGE(buf ^ 1, kc + 1); CP_WAIT1(); }
        else                    { CP_WAIT0(); }
        __syncthreads();
        const float* Wp = &Ws[buf][s][0];
        const float* Hp = &Hs[buf][tg * 4][0];
        #pragma unroll 4
        for (int kk = 0; kk < KC; kk += 4) {
            ulonglong2 w = *(const ulonglong2*)(Wp + kk);
            #pragma unroll
            for (int i = 0; i < 4; i++) {
                ulonglong2 hh = *(const ulonglong2*)(Hp + i * (KC + 4) + kk);
                fma2(acc[i], hh.x, w.x);
                fma2(acc[i], hh.y, w.y);
            }
        }
        __syncthreads();
        buf ^= 1;
    }
    #pragma unroll
    for (int i = 0; i < 4; i++) scS[tg * 4 + i][s] = hsum(acc[i]);
    __syncthreads();

    if (t < 32) {
        int token = tb + t;
        float v1 = -1e30f, v2 = -1e30f; int i1 = 0, i2 = 0;
        #pragma unroll
        for (int ss = 0; ss < NEXP; ss++) {
            float v = scS[t][ss];
            if (v > v1)      { v2 = v1; i2 = i1; v1 = v; i1 = ss; }
            else if (v > v2) { v2 = v;  i2 = ss; }
        }
        float Z = 0.f;
        #pragma unroll
        for (int ss = 0; ss < NEXP; ss++) Z += expf(scS[t][ss] - v1);
        float g1 = 1.f / Z;
        float g2 = expf(v2 - v1) / Z;
        float inv = 1.f / (g1 + g2 + 1e-8f);
        g1 *= inv; g2 *= inv;
        float scale = 0.9f + 0.2f * (g1 * d_aw[i1] + g2 * d_aw[i2]);
        d_coef[token * 2]     = scale * g1;
        d_coef[token * 2 + 1] = scale * g2;
        int p1 = atomicAdd(&d_cnt[i1], 1);
        if (p1 < CAP) d_items[i1 * CAP + p1] = token * 2;
        int p2 = atomicAdd(&d_cnt[i2], 1);
        if (p2 < CAP) d_items[i2 * CAP + p2] = token * 2 + 1;
    }
}

// ============ kernel 3a: moe1 — A[assign][16] = gathered H @ U[s] ==========
// Warp-broadcast design: lane = row-pair (m, m+32), warp w = k-eighth of
// each 64-k chunk (all lanes same k -> U reads are pure broadcast LDS.128).
// fma2 pairs r: {U[k][2j], U[k][2j+1]} x dup2(h[m][k]) -> A[2j], A[2j+1].
// U used in ORIGINAL [s][k][r] layout; no transpose. 8 k-partials reduced
// through smem (aliasing Hs) with coef folded at the end.
__global__ __launch_bounds__(256, 2) void moe1_kernel(
    const float* __restrict__ h, const float* __restrict__ U)
{
    __shared__ int   itemS[64];
    __shared__ float coefS[64];
    __shared__ float Hs[2][64][KC + 4];     // 34816 B (aliased by Ps in epilogue)
    __shared__ float Us[2][KC][RDIM];       //  8192 B, 64B rows (broadcast reads)

    int t    = threadIdx.x;
    int s    = blockIdx.x >> 4;
    int tile = blockIdx.x & 15;
    int n    = min(d_cnt[s], CAP);
    int base = tile * 64;
    if (base >= n) return;
    int cnt = min(64, n - base);

    if (t < 64) {
        if (t < cnt) {
            int item = d_items[s * CAP + base + t];
            itemS[t] = item;
            coefS[t] = d_coef[item];
        } else { itemS[t] = 0; coefS[t] = 0.f; }
    }
    __syncthreads();

    #define M1_STAGE(b, kc) {                                                 \
        int k0_ = (kc) * KC;                                                  \
        int row0 = t >> 4, q_ = t & 15;                                       \
        _Pragma("unroll")                                                     \
        for (int p = 0; p < 4; p++) {                                         \
            int row = row0 + 16 * p;                                          \
            int tok = itemS[row] >> 1;                                        \
            cpa16(&Hs[b][row][q_ * 4],                                        \
                  &h[(size_t)tok * HDIM + k0_ + q_ * 4]);                     \
        }                                                                     \
        {   int kk_ = t >> 2, q2 = t & 3;                                     \
            cpa16(&Us[b][kk_][q2 * 4],                                        \
                  &U[((size_t)s * HDIM + k0_ + kk_) * RDIM + q2 * 4]); }      \
        CP_COMMIT(); }

    int w    = t >> 5;        // warp -> k-eighth [w*8, w*8+8)
    int lane = t & 31;        // rows lane, lane+32

    u64 acc0[8], acc1[8];
    #pragma unroll
    for (int j = 0; j < 8; j++) { acc0[j] = 0ull; acc1[j] = 0ull; }

    M1_STAGE(0, 0);
    int buf = 0;
    for (int kc = 0; kc < HDIM / KC; kc++) {
        if (kc + 1 < HDIM / KC) { M1_STAGE(buf ^ 1, kc + 1); CP_WAIT1(); }
        else                    { CP_WAIT0(); }
        __syncthreads();
        const float* Hp0 = &Hs[buf][lane][w * 8];
        const float* Hp1 = &Hs[buf][lane + 32][w * 8];
        #pragma unroll
        for (int kb = 0; kb < 2; kb++) {
            float4 h0v = *(const float4*)(Hp0 + kb * 4);
            float4 h1v = *(const float4*)(Hp1 + kb * 4);
            const float* f0 = (const float*)&h0v;
            const float* f1 = (const float*)&h1v;
            #pragma unroll
            for (int ki = 0; ki < 4; ki++) {
                int k = w * 8 + kb * 4 + ki;
                ulonglong2 uA = *(const ulonglong2*)&Us[buf][k][0];
                ulonglong2 uB = *(const ulonglong2*)&Us[buf][k][4];
                ulonglong2 uC = *(const ulonglong2*)&Us[buf][k][8];
                ulonglong2 uD = *(const ulonglong2*)&Us[buf][k][12];
                u64 hh0 = dup2(f0[ki]);
                u64 hh1 = dup2(f1[ki]);
                fma2(acc0[0], hh0, uA.x); fma2(acc0[1], hh0, uA.y);
                fma2(acc0[2], hh0, uB.x); fma2(acc0[3], hh0, uB.y);
                fma2(acc0[4], hh0, uC.x); fma2(acc0[5], hh0, uC.y);
                fma2(acc0[6], hh0, uD.x); fma2(acc0[7], hh0, uD.y);
                fma2(acc1[0], hh1, uA.x); fma2(acc1[1], hh1, uA.y);
                fma2(acc1[2], hh1, uB.x); fma2(acc1[3], hh1, uB.y);
                fma2(acc1[4], hh1, uC.x); fma2(acc1[5], hh1, uC.y);
                fma2(acc1[6], hh1, uD.x); fma2(acc1[7], hh1, uD.y);
            }
        }
        __syncthreads();
        buf ^= 1;
    }

    // ---- epilogue: reduce 8 k-partials per row, fold coef, store A --------
    float* Ps = &Hs[0][0][0];              // 8 x 64 x 16 floats = 32KB (fits in Hs)
    #pragma unroll
    for (int j = 0; j < 8; j++) {
        *(u64*)&Ps[((w * 64 + lane) * 16) + 2 * j]        = acc0[j];
        *(u64*)&Ps[((w * 64 + lane + 32) * 16) + 2 * j]   = acc1[j];
    }
    __syncthreads();
    {
        int row = t >> 2, q = t & 3;
        float4 sum = make_float4(0.f, 0.f, 0.f, 0.f);
        #pragma unroll
        for (int w2 = 0; w2 < 8; w2++) {
            float4 p = *(const float4*)&Ps[((w2 * 64 + row) * 16) + q * 4];
            sum.x += p.x; sum.y += p.y; sum.z += p.z; sum.w += p.w;
        }
        float cf = coefS[row];
        sum.x *= cf; sum.y *= cf; sum.z *= cf; sum.w *= cf;
        *(float4*)&d_A[((size_t)(s * CAP + base + row)) * RDIM + q * 4] = sum;
    }
}

// ============ kernel 3b: moe2 — out[64][128] += A-tile @ Vp-chunk ==========
// grid = 32 experts x 16 row-tiles x 16 col-chunks = 8192 CTAs.
__global__ __launch_bounds__(256) void moe2_kernel(
    float* __restrict__ out)
{
    __shared__ int    itemS[64];
    __shared__ float  As[64][16];      // 64B rows: aligned; u64 reads broadcast
    __shared__ float2 Vs[8][130];      // 1040B rows = 65x16B (odd) -> conflict-free

    int t  = threadIdx.x;
    int s  = blockIdx.x >> 8;
    int rt = (blockIdx.x >> 4) & 15;
    int cc = blockIdx.x & 15;
    int n    = min(d_cnt[s], CAP);
    int base = rt * 64;
    if (base >= n) return;
    int cnt = min(64, n - base);

    if (t < 64) itemS[t] = (t < cnt) ? d_items[s * CAP + base + t] : -1;
    {   // stage A: 64 rows x 4 quads
        int m = t >> 2, q = t & 3;
        cpa16(&As[m][q * 4], &d_A[((size_t)(s * CAP + base + m)) * RDIM + q * 4]);
    }
    {   // stage Vp chunk: 8 rp x 128 cols (float2) = 512 x 16B
        #pragma unroll
        for (int j = 0; j < 2; j++) {
            int idx = t + 256 * j;
            int rp = idx >> 6, q = idx & 63;
            cpa16(&Vs[rp][q * 2],
                  &d_Vp[((size_t)(s * 8 + rp)) * HDIM + cc * 128 + q * 2]);
        }
    }
    CP_COMMIT(); CP_WAIT0();
    __syncthreads();

    int rg = t >> 5;            // warp -> 4-row group (per phase)
    int c0 = (t & 31) * 4;      // 4 cols per lane (contiguous per warp)

    #pragma unroll
    for (int ph = 0; ph < 2; ph++) {
        int rbase = ph * 32 + rg * 4;
        u64 oa[4][4];
        #pragma unroll
        for (int i = 0; i < 4; i++)
            #pragma unroll
            for (int j = 0; j < 4; j++) oa[i][j] = 0ull;

        #pragma unroll
        for (int rp = 0; rp < 8; rp++) {
            ulonglong2 v01 = *(const ulonglong2*)&Vs[rp][c0];
            ulonglong2 v23 = *(const ulonglong2*)&Vs[rp][c0 + 2];
            #pragma unroll
            for (int i = 0; i < 4; i++) {
                u64 ap = *(const u64*)&As[rbase + i][rp * 2];
                fma2(oa[i][0], ap, v01.x);
                fma2(oa[i][1], ap, v01.y);
                fma2(oa[i][2], ap, v23.x);
                fma2(oa[i][3], ap, v23.y);
            }
        }
        #pragma unroll
        for (int i = 0; i < 4; i++) {
            int row = rbase + i;
            if (row < cnt) {
                int token = itemS[row] >> 1;
                float* dst = out + (size_t)token * HDIM + cc * 128 + c0;
                red4(dst, hsum(oa[i][0]), hsum(oa[i][1]),
                          hsum(oa[i][2]), hsum(oa[i][3]));
            }
        }
    }
}

// ===========================================================================
extern "C" void kernel_launch(void* const* d_in, const int* in_sizes, int n_in,
                              void* d_out, int out_size)
{
    const float* h    = (const float*)d_in[0];
    const float* Wr   = (const float*)d_in[1];
    const float* U    = (const float*)d_in[2];
    const float* V    = (const float*)d_in[3];
    const float* attr = (const float*)d_in[4];
    const float* Wa   = (const float*)d_in[5];
    float* out = (float*)d_out;

    zero_kernel<<<NTOK * HDIM / 4 / 256, 256>>>(out);
    prep_kernel<<<512, 256>>>(V, attr, Wa);
    router_kernel<<<NTOK / 32, 256>>>(h, Wr);
    moe1_kernel<<<NEXP * 16, 256>>>(h, U);
    moe2_kernel<<<NEXP * 16 * 16, 256>>>(out);
}